// round 7
// baseline (speedup 1.0000x reference)
#include <cuda_runtime.h>
#include <cuda_fp16.h>

#define DB 8
#define DN 8192
#define DE 131072
#define DD 128
// 65536 rows total

__device__ float  g_h[DB * DN * DD];    // 32 MB: linear output (fp32)
__device__ __half g_hh[DB * DN * DD];   // 16 MB: fp16 copy for gathers
__device__ float  g_Wt[DD * DD];        // transposed weights (k-major)
__device__ int    g_cnt[DB * DN];       // per-dst edge counts
__device__ int    g_off[DB * DN];       // CSR start offsets
__device__ int    g_cur[DB * DN];       // scatter cursors
__device__ int    g_srt[DB * DE];       // src indices sorted by dst
__device__ int    g_base[DB];           // per-batch region allocator
__device__ int    g_is64;               // edge_index dtype flag

// ---------------------------------------------------------------------------
// setup: detect idx dtype + zero counters + transpose W. One kernel.
// ---------------------------------------------------------------------------
__global__ void setup_kernel(const unsigned* __restrict__ eiw,
                             const float* __restrict__ W) {
    int t = blockIdx.x * 256 + threadIdx.x;   // 65536 threads
    g_cnt[t] = 0;
    if (t < DB) g_base[t] = 0;
    if (t < DD * DD) {
        int k = t & 127;
        int c = t >> 7;
        g_Wt[k * DD + c] = W[c * DD + k];
    }
    if (t == 0) {
        // int64 values < 8192 -> all odd 32-bit words zero (little-endian)
        int ok = 1;
        for (int i = 0; i < 64; i++)
            if (eiw[2 * i + 1] != 0u) { ok = 0; break; }
        g_is64 = ok;
    }
}

__device__ __forceinline__ int load_idx(const void* ei, size_t p) {
    return g_is64 ? (int)((const long long*)ei)[p] : ((const int*)ei)[p];
}

// ---------------------------------------------------------------------------
// histogram of dst degrees
// ---------------------------------------------------------------------------
__global__ void hist_kernel(const void* __restrict__ ei) {
    int t = blockIdx.x * 256 + threadIdx.x;    // [0, DB*DE)
    int b = t >> 17;
    int e = t & (DE - 1);
    int dst = load_idx(ei, ((size_t)b * 2 + 1) * DE + e);
    if ((unsigned)dst < DN) atomicAdd(&g_cnt[b * DN + dst], 1);
}

// ---------------------------------------------------------------------------
// region allocation: warp-scan of counts + one atomicAdd per warp on the
// per-batch cursor. Regions are contiguous & disjoint (order arrival-based,
// which only permutes fp summation order — same as the atomic scatter).
// ---------------------------------------------------------------------------
__global__ void alloc_kernel() {
    int node = blockIdx.x * 256 + threadIdx.x;   // [0, 65536)
    int lane = threadIdx.x & 31;
    int b = node >> 13;
    int cnt = g_cnt[node];
    int incl = cnt;
#pragma unroll
    for (int o = 1; o < 32; o <<= 1) {
        int n = __shfl_up_sync(0xFFFFFFFFu, incl, o);
        if (lane >= o) incl += n;
    }
    int total = __shfl_sync(0xFFFFFFFFu, incl, 31);
    int base = 0;
    if (lane == 31) base = atomicAdd(&g_base[b], total);
    base = __shfl_sync(0xFFFFFFFFu, base, 31);
    int off = base + incl - cnt;
    g_off[node] = off;
    g_cur[node] = off;
}

// ---------------------------------------------------------------------------
// scatter src ids into dst-sorted order
// ---------------------------------------------------------------------------
__global__ void scatter_kernel(const void* __restrict__ ei) {
    int t = blockIdx.x * 256 + threadIdx.x;    // [0, DB*DE)
    int b = t >> 17;
    int e = t & (DE - 1);
    int src = load_idx(ei, (size_t)b * 2 * DE + e);
    int dst = load_idx(ei, ((size_t)b * 2 + 1) * DE + e);
    if ((unsigned)src >= DN || (unsigned)dst >= DN) return;
    int pos = atomicAdd(&g_cur[b * DN + dst], 1);
    g_srt[(size_t)b * DE + pos] = src;
}

// ---------------------------------------------------------------------------
// h = x @ W^T + b using packed f32x2 FMA (2 fp32 FMA / issue on sm_103a).
// Block = 256 thr, 128-row tile; warp = 16 rows x 128 cols, lane owns 4 cols
// (= 2 f32x2 pairs). x is stored in smem duplicated {x,x} so operand fetch is
// one LDS.128 broadcast per row per 2 k-steps. smem = 192 KB, 1 block/SM.
// Epilogue writes fp32 h and an fp16 copy for the gather stage.
// ---------------------------------------------------------------------------
__global__ void __launch_bounds__(256, 1)
gemm_kernel(const float* __restrict__ x, const float* __restrict__ bias) {
    extern __shared__ float sm[];
    float4* Ws4 = (float4*)sm;                     // W k-major: [128][32] float4 (64 KB)
    float4* xsd = (float4*)(sm + DD * DD);         // x dup: [128 rows][64] float4 (128 KB)

    const float4* Wt4 = (const float4*)g_Wt;
    for (int i = threadIdx.x; i < DD * DD / 4; i += 256) Ws4[i] = Wt4[i];

    int row0 = blockIdx.x * 128;
    const float4* x4 = (const float4*)(x + (size_t)row0 * DD);
    for (int i = threadIdx.x; i < 128 * 32; i += 256) {
        float4 v = x4[i];
        int row = i >> 5, j = i & 31;
        xsd[row * 64 + 2 * j]     = make_float4(v.x, v.x, v.y, v.y);
        xsd[row * 64 + 2 * j + 1] = make_float4(v.z, v.z, v.w, v.w);
    }
    __syncthreads();

    int warp = threadIdx.x >> 5;
    int lane = threadIdx.x & 31;
    int r0 = warp * 16;
    // per-row k-dup array: 128 ull per row; index k -> {x[k], x[k]}
    const unsigned long long* xr = (const unsigned long long*)(xsd + (size_t)r0 * 64);
    const unsigned long long* wp = (const unsigned long long*)Ws4;  // [128][64] ull

    unsigned long long acc[16][2];
#pragma unroll
    for (int r = 0; r < 16; r++) { acc[r][0] = 0ull; acc[r][1] = 0ull; }

#pragma unroll 2
    for (int k2 = 0; k2 < 64; k2++) {
        int k = 2 * k2;
        ulonglong2 w0 = ((const ulonglong2*)(wp + (size_t)k * 64 + 2 * lane))[0];
        ulonglong2 w1 = ((const ulonglong2*)(wp + (size_t)(k + 1) * 64 + 2 * lane))[0];
#pragma unroll
        for (int r = 0; r < 16; r++) {
            ulonglong2 xx = ((const ulonglong2*)(xr + (size_t)r * 128 + k))[0];
            asm("fma.rn.f32x2 %0, %1, %2, %0;" : "+l"(acc[r][0]) : "l"(w0.x), "l"(xx.x));
            asm("fma.rn.f32x2 %0, %1, %2, %0;" : "+l"(acc[r][1]) : "l"(w0.y), "l"(xx.x));
            asm("fma.rn.f32x2 %0, %1, %2, %0;" : "+l"(acc[r][0]) : "l"(w1.x), "l"(xx.y));
            asm("fma.rn.f32x2 %0, %1, %2, %0;" : "+l"(acc[r][1]) : "l"(w1.y), "l"(xx.y));
        }
    }

    float4 bb = ((const float4*)bias)[lane];
#pragma unroll
    for (int r = 0; r < 16; r++) {
        float2 lo = *(float2*)&acc[r][0];
        float2 hi = *(float2*)&acc[r][1];
        float4 o;
        o.x = lo.x + bb.x;
        o.y = lo.y + bb.y;
        o.z = hi.x + bb.z;
        o.w = hi.y + bb.w;
        size_t orow = (size_t)(row0 + r0 + r) * DD;
        ((float4*)(g_h + orow))[lane] = o;
        __half2 ha = __floats2half2_rn(o.x, o.y);
        __half2 hb = __floats2half2_rn(o.z, o.w);
        uint2 hp;
        hp.x = *(unsigned*)&ha;
        hp.y = *(unsigned*)&hb;
        ((uint2*)(g_hh + orow))[lane] = hp;
    }
}

// ---------------------------------------------------------------------------
// Fused: CSR gather of incident src rows (fp16), + fp32 h, LN, ReLU, mask.
// One warp per node; lane owns 4 consecutive cols (8B fp16 per neighbor row).
// ---------------------------------------------------------------------------
__global__ void agg_ln_kernel(const float* __restrict__ mask,
                              const float* __restrict__ gamma,
                              const float* __restrict__ beta,
                              float* __restrict__ out) {
    int w = (blockIdx.x * 256 + threadIdx.x) >> 5;   // node id [0, 65536)
    int lane = threadIdx.x & 31;
    int b = w >> 13;

    int start = g_off[w];
    int cnt = g_cnt[w];
    int end = start + cnt;
    const int* srt = g_srt + (size_t)b * DE;
    const __half* hb = g_hh + (size_t)b * DN * DD;

    float4 acc = make_float4(0.f, 0.f, 0.f, 0.f);
    int j = start;
    for (; j + 4 <= end; j += 4) {
        int s0 = srt[j], s1 = srt[j + 1], s2 = srt[j + 2], s3 = srt[j + 3];
        uint2 r0 = ((const uint2*)(hb + (size_t)s0 * DD))[lane];
        uint2 r1 = ((const uint2*)(hb + (size_t)s1 * DD))[lane];
        uint2 r2 = ((const uint2*)(hb + (size_t)s2 * DD))[lane];
        uint2 r3 = ((const uint2*)(hb + (size_t)s3 * DD))[lane];
        float2 a0 = __half22float2(*(__half2*)&r0.x), b0 = __half22float2(*(__half2*)&r0.y);
        float2 a1 = __half22float2(*(__half2*)&r1.x), b1 = __half22float2(*(__half2*)&r1.y);
        float2 a2 = __half22float2(*(__half2*)&r2.x), b2 = __half22float2(*(__half2*)&r2.y);
        float2 a3 = __half22float2(*(__half2*)&r3.x), b3 = __half22float2(*(__half2*)&r3.y);
        acc.x += (a0.x + a1.x) + (a2.x + a3.x);
        acc.y += (a0.y + a1.y) + (a2.y + a3.y);
        acc.z += (b0.x + b1.x) + (b2.x + b3.x);
        acc.w += (b0.y + b1.y) + (b2.y + b3.y);
    }
    for (; j < end; j++) {
        int s0 = srt[j];
        uint2 r0 = ((const uint2*)(hb + (size_t)s0 * DD))[lane];
        float2 a0 = __half22float2(*(__half2*)&r0.x), b0 = __half22float2(*(__half2*)&r0.y);
        acc.x += a0.x; acc.y += a0.y; acc.z += b0.x; acc.w += b0.y;
    }

    float4 h = ((const float4*)(g_h + (size_t)w * DD))[lane];
    const float s = 0.011048543456039806f;  // 1/sqrt(8192)
    float4 v;
    v.x = h.x + acc.x * s;
    v.y = h.y + acc.y * s;
    v.z = h.z + acc.z * s;
    v.w = h.w + acc.w * s;

    float sum = v.x + v.y + v.z + v.w;
    float ssq = v.x * v.x + v.y * v.y + v.z * v.z + v.w * v.w;
#pragma unroll
    for (int o = 16; o > 0; o >>= 1) {
        sum += __shfl_xor_sync(0xFFFFFFFFu, sum, o);
        ssq += __shfl_xor_sync(0xFFFFFFFFu, ssq, o);
    }
    float mu = sum * (1.0f / 128.0f);
    float var = ssq * (1.0f / 128.0f) - mu * mu;
    float rstd = rsqrtf(var + 1e-5f);
    float m = mask[w];

    float4 g = ((const float4*)gamma)[lane];
    float4 be = ((const float4*)beta)[lane];
    float4 o4;
    o4.x = fmaxf((v.x - mu) * rstd * g.x + be.x, 0.f) * m;
    o4.y = fmaxf((v.y - mu) * rstd * g.y + be.y, 0.f) * m;
    o4.z = fmaxf((v.z - mu) * rstd * g.z + be.z, 0.f) * m;
    o4.w = fmaxf((v.w - mu) * rstd * g.w + be.w, 0.f) * m;

    ((float4*)out)[(size_t)w * 32 + lane] = o4;
}

// ---------------------------------------------------------------------------
extern "C" void kernel_launch(void* const* d_in, const int* in_sizes, int n_in,
                              void* d_out, int out_size) {
    const float* xf     = (const float*)d_in[0];   // node_features [8,8192,128]
    const void*  ei     = d_in[1];                 // edge_index [8,2,131072]
    const float* mask   = (const float*)d_in[2];   // node_mask [8,8192]
    const float* W      = (const float*)d_in[3];   // W [128,128]
    const float* bias   = (const float*)d_in[4];   // b [128]
    const float* gamma  = (const float*)d_in[5];   // gamma [128]
    const float* beta   = (const float*)d_in[6];   // beta [128]
    float* out          = (float*)d_out;

    const int smem_bytes = (DD * DD + 128 * DD * 2) * 4;  // 64 KB + 128 KB = 192 KB
    cudaFuncSetAttribute(gemm_kernel, cudaFuncAttributeMaxDynamicSharedMemorySize, smem_bytes);

    setup_kernel<<<(DB * DN) / 256, 256>>>((const unsigned*)ei, W);
    hist_kernel<<<(DB * DE) / 256, 256>>>(ei);
    alloc_kernel<<<(DB * DN) / 256, 256>>>();
    gemm_kernel<<<(DB * DN) / 128, 256, smem_bytes>>>(xf, bias);   // 512 blocks
    scatter_kernel<<<(DB * DE) / 256, 256>>>(ei);
    agg_ln_kernel<<<(DB * DN) / 8, 256>>>(mask, gamma, beta, out); // 8192 blocks
}

// round 8
// speedup vs baseline: 1.4124x; 1.4124x over previous
#include <cuda_runtime.h>
#include <cuda_fp16.h>
#include <cuda_bf16.h>

#define DB 8
#define DN 8192
#define DE 131072
#define DD 128
// 65536 rows total

__device__ float  g_h[DB * DN * DD];    // 32 MB: linear output (fp32)
__device__ __half g_hh[DB * DN * DD];   // 16 MB: fp16 copy for gathers
__device__ float  g_Wt[DD * DD];        // transposed weights Wt[k][n] = W[n][k]
__device__ int    g_cnt[DB * DN];       // per-dst edge counts
__device__ int    g_off[DB * DN];       // CSR start offsets
__device__ int    g_cur[DB * DN];       // scatter cursors
__device__ int    g_srt[DB * DE];       // src indices sorted by dst
__device__ int    g_base[DB];           // per-batch region allocator
__device__ int    g_is64;               // edge_index dtype flag

// ---------------------------------------------------------------------------
// setup: detect idx dtype + zero counters + transpose W. One kernel.
// ---------------------------------------------------------------------------
__global__ void setup_kernel(const unsigned* __restrict__ eiw,
                             const float* __restrict__ W) {
    int t = blockIdx.x * 256 + threadIdx.x;   // 65536 threads
    g_cnt[t] = 0;
    if (t < DB) g_base[t] = 0;
    if (t < DD * DD) {
        int k = t & 127;
        int c = t >> 7;
        g_Wt[k * DD + c] = W[c * DD + k];
    }
    if (t == 0) {
        // int64 values < 8192 -> all odd 32-bit words zero (little-endian)
        int ok = 1;
        for (int i = 0; i < 64; i++)
            if (eiw[2 * i + 1] != 0u) { ok = 0; break; }
        g_is64 = ok;
    }
}

__device__ __forceinline__ int load_idx(const void* ei, size_t p) {
    return g_is64 ? (int)((const long long*)ei)[p] : ((const int*)ei)[p];
}

// ---------------------------------------------------------------------------
// histogram of dst degrees
// ---------------------------------------------------------------------------
__global__ void hist_kernel(const void* __restrict__ ei) {
    int t = blockIdx.x * 256 + threadIdx.x;    // [0, DB*DE)
    int b = t >> 17;
    int e = t & (DE - 1);
    int dst = load_idx(ei, ((size_t)b * 2 + 1) * DE + e);
    if ((unsigned)dst < DN) atomicAdd(&g_cnt[b * DN + dst], 1);
}

// ---------------------------------------------------------------------------
// region allocation: warp-scan of counts + one atomicAdd per warp on the
// per-batch cursor. Regions contiguous & disjoint.
// ---------------------------------------------------------------------------
__global__ void alloc_kernel() {
    int node = blockIdx.x * 256 + threadIdx.x;   // [0, 65536)
    int lane = threadIdx.x & 31;
    int b = node >> 13;
    int cnt = g_cnt[node];
    int incl = cnt;
#pragma unroll
    for (int o = 1; o < 32; o <<= 1) {
        int n = __shfl_up_sync(0xFFFFFFFFu, incl, o);
        if (lane >= o) incl += n;
    }
    int total = __shfl_sync(0xFFFFFFFFu, incl, 31);
    int base = 0;
    if (lane == 31) base = atomicAdd(&g_base[b], total);
    base = __shfl_sync(0xFFFFFFFFu, base, 31);
    int off = base + incl - cnt;
    g_off[node] = off;
    g_cur[node] = off;
}

// ---------------------------------------------------------------------------
// scatter src ids into dst-sorted order
// ---------------------------------------------------------------------------
__global__ void scatter_kernel(const void* __restrict__ ei) {
    int t = blockIdx.x * 256 + threadIdx.x;    // [0, DB*DE)
    int b = t >> 17;
    int e = t & (DE - 1);
    int src = load_idx(ei, (size_t)b * 2 * DE + e);
    int dst = load_idx(ei, ((size_t)b * 2 + 1) * DE + e);
    if ((unsigned)src >= DN || (unsigned)dst >= DN) return;
    int pos = atomicAdd(&g_cur[b * DN + dst], 1);
    g_srt[(size_t)b * DE + pos] = src;
}

// ---------------------------------------------------------------------------
// Tensor-core GEMM: h = x @ W^T + b via bf16 split (hi+lo) mma.sync.
// Block = 256 thr, 128-row tile; warp = 16 rows x 128 cols.
// smem: Whi/Wlo [k=128][n=128] bf16 + Xhi/Xlo [m=128][k=128] bf16 = 128 KB,
// all stored with XOR-swizzle (16B chunk j ^= row&7) -> conflict-free ldmatrix.
// Epilogue: fp32 g_h + fp16 g_hh.
// ---------------------------------------------------------------------------
__device__ __forceinline__ void ldsm_x4(unsigned* r, unsigned addr) {
    asm volatile("ldmatrix.sync.aligned.m8n8.x4.shared.b16 {%0,%1,%2,%3}, [%4];"
                 : "=r"(r[0]), "=r"(r[1]), "=r"(r[2]), "=r"(r[3]) : "r"(addr));
}
__device__ __forceinline__ void ldsm_x4_t(unsigned* r, unsigned addr) {
    asm volatile("ldmatrix.sync.aligned.m8n8.x4.trans.shared.b16 {%0,%1,%2,%3}, [%4];"
                 : "=r"(r[0]), "=r"(r[1]), "=r"(r[2]), "=r"(r[3]) : "r"(addr));
}
__device__ __forceinline__ void mma_bf16(float* c, const unsigned* a,
                                         unsigned b0, unsigned b1) {
    asm("mma.sync.aligned.m16n8k16.row.col.f32.bf16.bf16.f32 "
        "{%0,%1,%2,%3}, {%4,%5,%6,%7}, {%8,%9}, {%0,%1,%2,%3};"
        : "+f"(c[0]), "+f"(c[1]), "+f"(c[2]), "+f"(c[3])
        : "r"(a[0]), "r"(a[1]), "r"(a[2]), "r"(a[3]), "r"(b0), "r"(b1));
}

__device__ __forceinline__ void split8(float4 f0, float4 f1, uint4& hi, uint4& lo) {
    float f[8] = {f0.x, f0.y, f0.z, f0.w, f1.x, f1.y, f1.z, f1.w};
    unsigned h[4], l[4];
#pragma unroll
    for (int i = 0; i < 4; i++) {
        __nv_bfloat162 hh = __floats2bfloat162_rn(f[2 * i], f[2 * i + 1]);
        float r0 = f[2 * i]     - __bfloat162float(hh.x);
        float r1 = f[2 * i + 1] - __bfloat162float(hh.y);
        __nv_bfloat162 ll = __floats2bfloat162_rn(r0, r1);
        h[i] = *(unsigned*)&hh;
        l[i] = *(unsigned*)&ll;
    }
    hi = make_uint4(h[0], h[1], h[2], h[3]);
    lo = make_uint4(l[0], l[1], l[2], l[3]);
}

__global__ void __launch_bounds__(256)
gemm_kernel(const float* __restrict__ x, const float* __restrict__ bias) {
    extern __shared__ char smc[];
    __nv_bfloat16* sWhi = (__nv_bfloat16*)smc;              // [128][128] swz
    __nv_bfloat16* sXhi = (__nv_bfloat16*)(smc + 65536);    // [128][128] swz
    // lo planes at +32768 bytes from each hi plane

    int tid = threadIdx.x;
    int row0 = blockIdx.x * 128;

    // load + split W (g_Wt is [k][n] fp32), 16B chunks with swizzle
    for (int c = tid; c < 2048; c += 256) {
        int row = c >> 4, j = c & 15;
        const float4* p = (const float4*)(g_Wt + row * DD + j * 8);
        uint4 hi, lo;
        split8(p[0], p[1], hi, lo);
        int off = row * DD + ((j ^ (row & 7)) << 3);
        *(uint4*)(sWhi + off)                 = hi;
        *(uint4*)((char*)(sWhi + off) + 32768) = lo;
    }
    // load + split X
    for (int c = tid; c < 2048; c += 256) {
        int row = c >> 4, j = c & 15;
        const float4* p = (const float4*)(x + (size_t)(row0 + row) * DD + j * 8);
        uint4 hi, lo;
        split8(p[0], p[1], hi, lo);
        int off = row * DD + ((j ^ (row & 7)) << 3);
        *(uint4*)(sXhi + off)                 = hi;
        *(uint4*)((char*)(sXhi + off) + 32768) = lo;
    }
    __syncthreads();

    int warp = tid >> 5, lane = tid & 31;
    int m0 = warp * 16;
    int l15 = lane & 15, lh = lane >> 4;

    int arow = m0 + l15;
    unsigned xbhi = (unsigned)__cvta_generic_to_shared(sXhi) + arow * 256;
    unsigned xsw = (unsigned)(arow & 7);
    unsigned wb = (unsigned)__cvta_generic_to_shared(sWhi);

    float acc[16][4];
#pragma unroll
    for (int t = 0; t < 16; t++)
#pragma unroll
        for (int i = 0; i < 4; i++) acc[t][i] = 0.f;

#pragma unroll
    for (int kt = 0; kt < 8; kt++) {
        unsigned ahi[4], alo[4];
        unsigned achunk = (((unsigned)(2 * kt + lh)) ^ xsw) << 4;
        ldsm_x4(ahi, xbhi + achunk);
        ldsm_x4(alo, xbhi + achunk + 32768u);
        int brow = kt * 16 + l15;
        unsigned bb = wb + brow * 256;
        unsigned bsw = (unsigned)(brow & 7);
#pragma unroll
        for (int t2 = 0; t2 < 8; t2++) {
            unsigned bhi[4], blo[4];
            unsigned bchunk = (((unsigned)(2 * t2 + lh)) ^ bsw) << 4;
            ldsm_x4_t(bhi, bb + bchunk);
            ldsm_x4_t(blo, bb + bchunk + 32768u);
            mma_bf16(acc[2 * t2],     ahi, bhi[0], bhi[1]);
            mma_bf16(acc[2 * t2 + 1], ahi, bhi[2], bhi[3]);
            mma_bf16(acc[2 * t2],     alo, bhi[0], bhi[1]);
            mma_bf16(acc[2 * t2 + 1], alo, bhi[2], bhi[3]);
            mma_bf16(acc[2 * t2],     ahi, blo[0], blo[1]);
            mma_bf16(acc[2 * t2 + 1], ahi, blo[2], blo[3]);
        }
    }

    // epilogue: C frag lane mapping: rows g, g+8; cols 8t + 2q (+1)
    int g = lane >> 2;
    int q = lane & 3;
    size_t r0g = (size_t)(row0 + m0 + g) * DD;
    float*  h0  = g_h  + r0g;
    float*  h1  = h0 + 8 * DD;
    __half* hh0 = g_hh + r0g;
    __half* hh1 = hh0 + 8 * DD;
#pragma unroll
    for (int t = 0; t < 16; t++) {
        int n = 8 * t + 2 * q;
        float2 bv = *(const float2*)(bias + n);
        float2 v0 = make_float2(acc[t][0] + bv.x, acc[t][1] + bv.y);
        float2 v1 = make_float2(acc[t][2] + bv.x, acc[t][3] + bv.y);
        *(float2*)(h0 + n) = v0;
        *(float2*)(h1 + n) = v1;
        *(__half2*)(hh0 + n) = __floats2half2_rn(v0.x, v0.y);
        *(__half2*)(hh1 + n) = __floats2half2_rn(v1.x, v1.y);
    }
}

// ---------------------------------------------------------------------------
// Fused: CSR gather of incident src rows (fp16), + fp32 h, LN, ReLU, mask.
// One warp per node; lane owns 4 consecutive cols.
// ---------------------------------------------------------------------------
__global__ void agg_ln_kernel(const float* __restrict__ mask,
                              const float* __restrict__ gamma,
                              const float* __restrict__ beta,
                              float* __restrict__ out) {
    int w = (blockIdx.x * 256 + threadIdx.x) >> 5;   // node id [0, 65536)
    int lane = threadIdx.x & 31;
    int b = w >> 13;

    int start = g_off[w];
    int cnt = g_cnt[w];
    int end = start + cnt;
    const int* srt = g_srt + (size_t)b * DE;
    const __half* hb = g_hh + (size_t)b * DN * DD;

    float4 acc = make_float4(0.f, 0.f, 0.f, 0.f);
    int j = start;
    for (; j + 4 <= end; j += 4) {
        int s0 = srt[j], s1 = srt[j + 1], s2 = srt[j + 2], s3 = srt[j + 3];
        uint2 r0 = ((const uint2*)(hb + (size_t)s0 * DD))[lane];
        uint2 r1 = ((const uint2*)(hb + (size_t)s1 * DD))[lane];
        uint2 r2 = ((const uint2*)(hb + (size_t)s2 * DD))[lane];
        uint2 r3 = ((const uint2*)(hb + (size_t)s3 * DD))[lane];
        float2 a0 = __half22float2(*(__half2*)&r0.x), b0 = __half22float2(*(__half2*)&r0.y);
        float2 a1 = __half22float2(*(__half2*)&r1.x), b1 = __half22float2(*(__half2*)&r1.y);
        float2 a2 = __half22float2(*(__half2*)&r2.x), b2 = __half22float2(*(__half2*)&r2.y);
        float2 a3 = __half22float2(*(__half2*)&r3.x), b3 = __half22float2(*(__half2*)&r3.y);
        acc.x += (a0.x + a1.x) + (a2.x + a3.x);
        acc.y += (a0.y + a1.y) + (a2.y + a3.y);
        acc.z += (b0.x + b1.x) + (b2.x + b3.x);
        acc.w += (b0.y + b1.y) + (b2.y + b3.y);
    }
    for (; j < end; j++) {
        int s0 = srt[j];
        uint2 r0 = ((const uint2*)(hb + (size_t)s0 * DD))[lane];
        float2 a0 = __half22float2(*(__half2*)&r0.x), b0 = __half22float2(*(__half2*)&r0.y);
        acc.x += a0.x; acc.y += a0.y; acc.z += b0.x; acc.w += b0.y;
    }

    float4 h = ((const float4*)(g_h + (size_t)w * DD))[lane];
    const float s = 0.011048543456039806f;  // 1/sqrt(8192)
    float4 v;
    v.x = h.x + acc.x * s;
    v.y = h.y + acc.y * s;
    v.z = h.z + acc.z * s;
    v.w = h.w + acc.w * s;

    float sum = v.x + v.y + v.z + v.w;
    float ssq = v.x * v.x + v.y * v.y + v.z * v.z + v.w * v.w;
#pragma unroll
    for (int o = 16; o > 0; o >>= 1) {
        sum += __shfl_xor_sync(0xFFFFFFFFu, sum, o);
        ssq += __shfl_xor_sync(0xFFFFFFFFu, ssq, o);
    }
    float mu = sum * (1.0f / 128.0f);
    float var = ssq * (1.0f / 128.0f) - mu * mu;
    float rstd = rsqrtf(var + 1e-5f);
    float m = mask[w];

    float4 gg = ((const float4*)gamma)[lane];
    float4 be = ((const float4*)beta)[lane];
    float4 o4;
    o4.x = fmaxf((v.x - mu) * rstd * gg.x + be.x, 0.f) * m;
    o4.y = fmaxf((v.y - mu) * rstd * gg.y + be.y, 0.f) * m;
    o4.z = fmaxf((v.z - mu) * rstd * gg.z + be.z, 0.f) * m;
    o4.w = fmaxf((v.w - mu) * rstd * gg.w + be.w, 0.f) * m;

    ((float4*)out)[(size_t)w * 32 + lane] = o4;
}

// ---------------------------------------------------------------------------
extern "C" void kernel_launch(void* const* d_in, const int* in_sizes, int n_in,
                              void* d_out, int out_size) {
    const float* xf     = (const float*)d_in[0];   // node_features [8,8192,128]
    const void*  ei     = d_in[1];                 // edge_index [8,2,131072]
    const float* mask   = (const float*)d_in[2];   // node_mask [8,8192]
    const float* W      = (const float*)d_in[3];   // W [128,128]
    const float* bias   = (const float*)d_in[4];   // b [128]
    const float* gamma  = (const float*)d_in[5];   // gamma [128]
    const float* beta   = (const float*)d_in[6];   // beta [128]
    float* out          = (float*)d_out;

    const int smem_bytes = 131072;  // 4 x 32 KB bf16 planes
    cudaFuncSetAttribute(gemm_kernel, cudaFuncAttributeMaxDynamicSharedMemorySize, smem_bytes);

    setup_kernel<<<(DB * DN) / 256, 256>>>((const unsigned*)ei, W);
    hist_kernel<<<(DB * DE) / 256, 256>>>(ei);
    alloc_kernel<<<(DB * DN) / 256, 256>>>();
    gemm_kernel<<<(DB * DN) / 128, 256, smem_bytes>>>(xf, bias);   // 512 blocks
    scatter_kernel<<<(DB * DE) / 256, 256>>>(ei);
    agg_ln_kernel<<<(DB * DN) / 8, 256>>>(mask, gamma, beta, out); // 8192 blocks
}